// round 11
// baseline (speedup 1.0000x reference)
#include <cuda_runtime.h>
#include <cstdint>

#define BB    8
#define MM    4096
#define WW    128
#define CC    32
#define NNK   16
#define NROW  (BB*MM)          // 32768
#define NEL   (NROW*CC)        // 1048576
#define NNE   (MM*NNK)         // 65536
#define FCIN  (MM*CC)          // 131072
#define HID   256
#define NOUT  53

// ---------------- scratch (static device memory; no allocations) ----------------
__device__ float g_attn0[NNE];
__device__ float g_attn1[NNE];
__device__ int   g_cols[NNE];
__device__ float g_wT0[128*64];
__device__ float g_wT1[32*64];
__device__ float g_bias0[32];
__device__ float g_bias1[32];
__device__ float g_y1[NEL];
__device__ float g_y2[NEL];
__device__ float g_h0[NEL];
__device__ float g_h1[NEL];
__device__ float g_stats[128];         // [0..63]=layer0 sum/sumsq, [64..127]=layer1
__device__ float g_scale0[32], g_shift0[32];
__device__ float g_scale1[32], g_shift1[32];
__device__ float g_acc[BB*HID];        // fc1 accumulators

// ---------------- zero accumulators ----------------
__global__ void k_zero()
{
    int t = threadIdx.x;
    if (t < 128) g_stats[t] = 0.f;
    for (int i = t; i < BB*HID; i += 256) g_acc[i] = 0.f;
}

// ---------------- edge attention: GMM weights + softmax(16) + dedupe ----------------
__global__ void k_attn(const float* __restrict__ pseudo, const int* __restrict__ L_idx,
                       const float* __restrict__ ew, const float* __restrict__ eb,
                       const float* __restrict__ mu0, const float* __restrict__ sg0,
                       const float* __restrict__ mu1, const float* __restrict__ sg1)
{
    int e = blockIdx.x * 256 + threadIdx.x;      // grid covers NNE exactly
    float p0 = pseudo[2*e], p1 = pseudo[2*e+1];
    float emb[5];
#pragma unroll
    for (int d = 0; d < 5; d++)
        emb[d] = fmaf(p0, __ldg(&ew[2*d]), fmaf(p1, __ldg(&ew[2*d+1]), __ldg(&eb[d])));
    float w0 = 0.f, w1 = 0.f;
#pragma unroll
    for (int j = 0; j < 4; j++) {
        float q0 = 0.f, q1 = 0.f;
#pragma unroll
        for (int d = 0; d < 5; d++) {
            float u0 = emb[d] - __ldg(&mu0[j*5+d]);
            q0 = fmaf(u0*u0, __ldg(&sg0[j*5+d]), q0);
            float u1 = emb[d] - __ldg(&mu1[j*5+d]);
            q1 = fmaf(u1*u1, __ldg(&sg1[j*5+d]), q1);
        }
        w0 += expf(-0.5f*q0);
        w1 += expf(-0.5f*q1);
    }
    // softmax within groups of 16 lanes (xor-shuffles stay inside the group)
    float m0 = w0, m1 = w1;
#pragma unroll
    for (int off = 8; off; off >>= 1) {
        m0 = fmaxf(m0, __shfl_xor_sync(0xffffffffu, m0, off));
        m1 = fmaxf(m1, __shfl_xor_sync(0xffffffffu, m1, off));
    }
    float e0 = expf(w0 - m0), e1 = expf(w1 - m1);
    float s0 = e0, s1 = e1;
#pragma unroll
    for (int off = 8; off; off >>= 1) {
        s0 += __shfl_xor_sync(0xffffffffu, s0, off);
        s1 += __shfl_xor_sync(0xffffffffu, s1, off);
    }
    float a0 = e0 / s0, a1 = e1 / s1;

    int m   = e >> 4;
    int col = L_idx[e] - m * MM;
    int lane = threadIdx.x & 31, kloc = lane & 15, gb = lane & 16;
    // scatter-with-set semantics: on duplicate column within a row, LAST write wins
    bool dead = false;
#pragma unroll
    for (int kk = 0; kk < 16; kk++) {
        int oc = __shfl_sync(0xffffffffu, col, gb | kk);
        if (kk > kloc && oc == col) dead = true;
    }
    g_attn0[e] = dead ? 0.f : a0;
    g_attn1[e] = dead ? 0.f : a1;
    g_cols[e]  = col;
}

// ---------------- weight prep: transpose to [k][64] and combine biases ----------------
__global__ void k_prepw(const float* __restrict__ l1w0, const float* __restrict__ l1b0,
                        const float* __restrict__ l2w0, const float* __restrict__ l2b0,
                        const float* __restrict__ l1w1, const float* __restrict__ l1b1,
                        const float* __restrict__ l2w1, const float* __restrict__ l2b1)
{
    int t = threadIdx.x;
    for (int i = t; i < 128*64; i += 256) {
        int k = i >> 6, c = i & 63;
        g_wT0[i] = (c < 32) ? l1w0[c*128 + k] : l2w0[(c-32)*128 + k];
    }
    for (int i = t; i < 32*64; i += 256) {
        int k = i >> 6, c = i & 63;
        g_wT1[i] = (c < 32) ? l1w1[c*32 + k] : l2w1[(c-32)*32 + k];
    }
    if (t < 32) {
        g_bias0[t] = l1b0[t] + l2b0[t];
        g_bias1[t] = l1b1[t] + l2b1[t];
    }
}

// ---------------- projection GEMM: (16 rows x K) @ (K x 64), 4x4 register tile ----------------
// LAYER1 applies BN0 scale/shift + relu while staging inputs.
template<int K, bool LAYER1>
__global__ void __launch_bounds__(64) k_proj(const float* __restrict__ in_)
{
    constexpr int STR = 20;                      // k-stride in shared (float4-aligned)
    __shared__ __align__(16) float xs[K * STR];
    const float* in = LAYER1 ? g_h0 : in_;
    const float* wT = LAYER1 ? g_wT1 : g_wT0;
    int t = threadIdx.x;
    int row0 = blockIdx.x * 16;

    for (int i = t; i < 16 * K; i += 64) {
        int r = i / K, k = i - r * K;
        float v = in[(size_t)(row0 + r) * K + k];
        if (LAYER1) v = fmaxf(0.f, fmaf(v, g_scale0[k], g_shift0[k]));
        xs[k * STR + r] = v;
    }
    __syncthreads();

    int cg = t & 15, rg = t >> 4;                // 16 col-groups x 4 row-groups
    float acc[4][4] = {};
    const float4* w4 = reinterpret_cast<const float4*>(wT);
#pragma unroll 8
    for (int k = 0; k < K; k++) {
        float4 xv = *reinterpret_cast<const float4*>(&xs[k * STR + rg * 4]);
        float4 wv = __ldg(&w4[k * 16 + cg]);
        float xa[4] = {xv.x, xv.y, xv.z, xv.w};
        float wa[4] = {wv.x, wv.y, wv.z, wv.w};
#pragma unroll
        for (int r = 0; r < 4; r++)
#pragma unroll
            for (int c = 0; c < 4; c++)
                acc[r][c] = fmaf(xa[r], wa[c], acc[r][c]);
    }

    float* dst = (cg < 8) ? g_y1 : g_y2;
    int cb = (cg < 8) ? cg * 4 : (cg - 8) * 4;
#pragma unroll
    for (int r = 0; r < 4; r++) {
        int row = row0 + rg * 4 + r;
        float4 v = make_float4(acc[r][0], acc[r][1], acc[r][2], acc[r][3]);
        *reinterpret_cast<float4*>(&dst[row * 32 + cb]) = v;
    }
}

// ---------------- sparse graph conv: warp per (b,m), lane per channel ----------------
__global__ void k_conv(int layer)
{
    int warp = threadIdx.x >> 5, lane = threadIdx.x & 31;
    int pair = blockIdx.x * 8 + warp;            // pair = b*M + m
    int m    = pair & (MM - 1);
    const float* attn = layer ? g_attn1 : g_attn0;
    const float* bias = layer ? g_bias1 : g_bias0;
    float* out        = layer ? g_h1   : g_h0;
    int base = m * NNK;
    int boff = pair - m;                         // b*M
    float acc = bias[lane] + g_y2[pair * 32 + lane];
#pragma unroll
    for (int k = 0; k < NNK; k++) {
        float a  = __ldg(&attn[base + k]);
        int col  = __ldg(&g_cols[base + k]);
        acc = fmaf(a, g_y1[(boff + col) * 32 + lane], acc);
    }
    out[pair * 32 + lane] = acc;
}

// ---------------- BN stats (sum & sumsq per channel) ----------------
__global__ void k_stats(int layer)
{
    const float* h = layer ? g_h1 : g_h0;
    float* st = g_stats + layer * 64;
    int t = threadIdx.x;
    float s = 0.f, q = 0.f;
    for (int i = blockIdx.x * 256 + t; i < NEL; i += 65536) {
        float v = h[i];
        s += v; q = fmaf(v, v, q);
    }
    __shared__ float ss[256], sq[256];
    ss[t] = s; sq[t] = q;
    __syncthreads();
    if (t < 32) {
#pragma unroll
        for (int w = 1; w < 8; w++) { s += ss[t + 32*w]; q += sq[t + 32*w]; }
        atomicAdd(&st[t], s);
        atomicAdd(&st[32 + t], q);
    }
}

// ---------------- BN scale/shift from stats ----------------
__global__ void k_bnscale(int layer, const float* __restrict__ g, const float* __restrict__ b)
{
    int t = threadIdx.x;
    if (t >= 32) return;
    const float* st = g_stats + layer * 64;
    float inv_n = 1.f / (float)NROW;
    float mean = st[t] * inv_n;
    float var  = st[32 + t] * inv_n - mean * mean;
    float sc = g[t] * rsqrtf(var + 1e-5f);
    float sh = b[t] - mean * sc;
    if (layer) { g_scale1[t] = sc; g_shift1[t] = sh; }
    else       { g_scale0[t] = sc; g_shift0[t] = sh; }
}

// ---------------- FC1 split-K: grid (128 i-segments, 8 o-tiles of 32) ----------------
__global__ void __launch_bounds__(256) k_fc1(const float* __restrict__ w)
{
    __shared__ float fs[8 * 1024];
    int seg = blockIdx.x, ot = blockIdx.y, t = threadIdx.x;
    int ibase = seg * 1024;
    for (int idx = t; idx < 8192; idx += 256) {
        int b = idx >> 10, ii = idx & 1023;
        float v = g_h1[b * FCIN + ibase + ii];
        fs[idx] = fmaxf(0.f, fmaf(v, g_scale1[ii & 31], g_shift1[ii & 31]));
    }
    __syncthreads();

    int warp = t >> 5, lane = t & 31;
    int o0 = ot * 32 + warp * 4;
    float a[4][8] = {};
    for (int ii = lane; ii < 1024; ii += 32) {
        float f[8];
#pragma unroll
        for (int b = 0; b < 8; b++) f[b] = fs[b * 1024 + ii];
#pragma unroll
        for (int oo = 0; oo < 4; oo++) {
            float wv = __ldg(&w[(size_t)(o0 + oo) * FCIN + ibase + ii]);
#pragma unroll
            for (int b = 0; b < 8; b++) a[oo][b] = fmaf(wv, f[b], a[oo][b]);
        }
    }
#pragma unroll
    for (int oo = 0; oo < 4; oo++)
#pragma unroll
        for (int b = 0; b < 8; b++) {
            float v = a[oo][b];
#pragma unroll
            for (int off = 16; off; off >>= 1) v += __shfl_xor_sync(0xffffffffu, v, off);
            if (lane == 0) atomicAdd(&g_acc[b * HID + o0 + oo], v);
        }
}

// ---------------- FC2: out[b][j] = relu(acc+fc1b) . fc2w[j] + fc2b[j] ----------------
__global__ void k_fc2(const float* __restrict__ fc1b, const float* __restrict__ w2,
                      const float* __restrict__ b2, float* __restrict__ out)
{
    int j = blockIdx.x;                          // 0..52
    int b = threadIdx.x >> 5, lane = threadIdx.x & 31;
    float s = 0.f;
    for (int o = lane; o < HID; o += 32) {
        float a = fmaxf(0.f, g_acc[b * HID + o] + __ldg(&fc1b[o]));
        s = fmaf(a, __ldg(&w2[j * HID + o]), s);
    }
#pragma unroll
    for (int off = 16; off; off >>= 1) s += __shfl_xor_sync(0xffffffffu, s, off);
    if (lane == 0) out[b * NOUT + j] = s + b2[j];
}

// ---------------- launch ----------------
extern "C" void kernel_launch(void* const* d_in, const int* in_sizes, int n_in,
                              void* d_out, int out_size)
{
    const float* x      = (const float*)d_in[0];
    const float* pseudo = (const float*)d_in[1];
    const int*   L_idx  = (const int*)  d_in[2];
    const float* ew   = (const float*)d_in[3];
    const float* eb   = (const float*)d_in[4];
    const float* mu0  = (const float*)d_in[5];
    const float* sg0  = (const float*)d_in[6];
    const float* mu1  = (const float*)d_in[7];
    const float* sg1  = (const float*)d_in[8];
    const float* l1w0 = (const float*)d_in[9];
    const float* l1b0 = (const float*)d_in[10];
    const float* l2w0 = (const float*)d_in[11];
    const float* l2b0 = (const float*)d_in[12];
    const float* l1w1 = (const float*)d_in[13];
    const float* l1b1 = (const float*)d_in[14];
    const float* l2w1 = (const float*)d_in[15];
    const float* l2b1 = (const float*)d_in[16];
    const float* bng0 = (const float*)d_in[17];
    const float* bnb0 = (const float*)d_in[18];
    const float* bng1 = (const float*)d_in[19];
    const float* bnb1 = (const float*)d_in[20];
    const float* fc1w = (const float*)d_in[21];
    const float* fc1b = (const float*)d_in[22];
    const float* fc2w = (const float*)d_in[23];
    const float* fc2b = (const float*)d_in[24];
    float* out = (float*)d_out;

    k_zero<<<1, 256>>>();
    k_attn<<<NNE/256, 256>>>(pseudo, L_idx, ew, eb, mu0, sg0, mu1, sg1);
    k_prepw<<<1, 256>>>(l1w0, l1b0, l2w0, l2b0, l1w1, l1b1, l2w1, l2b1);

    // layer 0
    k_proj<128, false><<<NROW/16, 64>>>(x);
    k_conv<<<NROW/8, 256>>>(0);
    k_stats<<<256, 256>>>(0);
    k_bnscale<<<1, 32>>>(0, bng0, bnb0);

    // layer 1 (BN0+relu folded into proj staging)
    k_proj<32, true><<<NROW/16, 64>>>(x);
    k_conv<<<NROW/8, 256>>>(1);
    k_stats<<<256, 256>>>(1);
    k_bnscale<<<1, 32>>>(1, bng1, bnb1);

    // FC head (BN1+relu folded into fc1 staging)
    k_fc1<<<dim3(128, 8), 256>>>(fc1w);
    k_fc2<<<NOUT, 256>>>(fc1b, fc2w, fc2b, out);
}

// round 12
// speedup vs baseline: 1.0050x; 1.0050x over previous
#include <cuda_runtime.h>
#include <cstdint>

#define BB    8
#define MM    4096
#define WW    128
#define CC    32
#define NNK   16
#define NROW  (BB*MM)          // 32768
#define NEL   (NROW*CC)        // 1048576
#define NNE   (MM*NNK)         // 65536
#define FCIN  (MM*CC)          // 131072
#define HID   256
#define NOUT  53

// ---------------- scratch (static device memory; no allocations) ----------------
__device__ float g_attn0[NNE];
__device__ float g_attn1[NNE];
__device__ int   g_cols[NNE];
__device__ float g_wT0[128*64];
__device__ float g_wT1[32*64];
__device__ float g_bias0[32];
__device__ float g_bias1[32];
__device__ float g_y1[NEL];
__device__ float g_y2[NEL];
__device__ float g_h0[NEL];
__device__ float g_h1[NEL];
__device__ float g_stats[128];         // [0..63]=layer0 sum/sumsq, [64..127]=layer1
__device__ float g_scale0[32], g_shift0[32];
__device__ float g_scale1[32], g_shift1[32];
__device__ float g_acc[BB*HID];        // fc1 accumulators

// ---------------- zero accumulators ----------------
__global__ void k_zero()
{
    int t = threadIdx.x;
    if (t < 128) g_stats[t] = 0.f;
    for (int i = t; i < BB*HID; i += 256) g_acc[i] = 0.f;
}

// ---------------- edge attention: GMM weights + softmax(16) + dedupe ----------------
__global__ void k_attn(const float* __restrict__ pseudo, const int* __restrict__ L_idx,
                       const float* __restrict__ ew, const float* __restrict__ eb,
                       const float* __restrict__ mu0, const float* __restrict__ sg0,
                       const float* __restrict__ mu1, const float* __restrict__ sg1)
{
    int e = blockIdx.x * 256 + threadIdx.x;      // grid covers NNE exactly
    float p0 = pseudo[2*e], p1 = pseudo[2*e+1];
    float emb[5];
#pragma unroll
    for (int d = 0; d < 5; d++)
        emb[d] = fmaf(p0, __ldg(&ew[2*d]), fmaf(p1, __ldg(&ew[2*d+1]), __ldg(&eb[d])));
    float w0 = 0.f, w1 = 0.f;
#pragma unroll
    for (int j = 0; j < 4; j++) {
        float q0 = 0.f, q1 = 0.f;
#pragma unroll
        for (int d = 0; d < 5; d++) {
            float u0 = emb[d] - __ldg(&mu0[j*5+d]);
            q0 = fmaf(u0*u0, __ldg(&sg0[j*5+d]), q0);
            float u1 = emb[d] - __ldg(&mu1[j*5+d]);
            q1 = fmaf(u1*u1, __ldg(&sg1[j*5+d]), q1);
        }
        w0 += expf(-0.5f*q0);
        w1 += expf(-0.5f*q1);
    }
    // softmax within groups of 16 lanes (xor-shuffles stay inside the group)
    float m0 = w0, m1 = w1;
#pragma unroll
    for (int off = 8; off; off >>= 1) {
        m0 = fmaxf(m0, __shfl_xor_sync(0xffffffffu, m0, off));
        m1 = fmaxf(m1, __shfl_xor_sync(0xffffffffu, m1, off));
    }
    float e0 = expf(w0 - m0), e1 = expf(w1 - m1);
    float s0 = e0, s1 = e1;
#pragma unroll
    for (int off = 8; off; off >>= 1) {
        s0 += __shfl_xor_sync(0xffffffffu, s0, off);
        s1 += __shfl_xor_sync(0xffffffffu, s1, off);
    }
    float a0 = e0 / s0, a1 = e1 / s1;

    int m   = e >> 4;
    int col = L_idx[e] - m * MM;
    int lane = threadIdx.x & 31, kloc = lane & 15, gb = lane & 16;
    // scatter-with-set semantics: on duplicate column within a row, LAST write wins
    bool dead = false;
#pragma unroll
    for (int kk = 0; kk < 16; kk++) {
        int oc = __shfl_sync(0xffffffffu, col, gb | kk);
        if (kk > kloc && oc == col) dead = true;
    }
    g_attn0[e] = dead ? 0.f : a0;
    g_attn1[e] = dead ? 0.f : a1;
    g_cols[e]  = col;
}

// ---------------- weight prep: transpose to [k][64] and combine biases ----------------
__global__ void k_prepw(const float* __restrict__ l1w0, const float* __restrict__ l1b0,
                        const float* __restrict__ l2w0, const float* __restrict__ l2b0,
                        const float* __restrict__ l1w1, const float* __restrict__ l1b1,
                        const float* __restrict__ l2w1, const float* __restrict__ l2b1)
{
    int t = threadIdx.x;
    for (int i = t; i < 128*64; i += 256) {
        int k = i >> 6, c = i & 63;
        g_wT0[i] = (c < 32) ? l1w0[c*128 + k] : l2w0[(c-32)*128 + k];
    }
    for (int i = t; i < 32*64; i += 256) {
        int k = i >> 6, c = i & 63;
        g_wT1[i] = (c < 32) ? l1w1[c*32 + k] : l2w1[(c-32)*32 + k];
    }
    if (t < 32) {
        g_bias0[t] = l1b0[t] + l2b0[t];
        g_bias1[t] = l1b1[t] + l2b1[t];
    }
}

// ---------------- projection GEMM: (16 rows x K) @ (K x 64), 4x4 register tile ----------------
// LAYER1 applies BN0 scale/shift + relu while staging inputs.
template<int K, bool LAYER1>
__global__ void __launch_bounds__(64) k_proj(const float* __restrict__ in_)
{
    constexpr int STR = 20;                      // k-stride in shared (float4-aligned)
    __shared__ __align__(16) float xs[K * STR];
    const float* in = LAYER1 ? g_h0 : in_;
    const float* wT = LAYER1 ? g_wT1 : g_wT0;
    int t = threadIdx.x;
    int row0 = blockIdx.x * 16;

    for (int i = t; i < 16 * K; i += 64) {
        int r = i / K, k = i - r * K;
        float v = in[(size_t)(row0 + r) * K + k];
        if (LAYER1) v = fmaxf(0.f, fmaf(v, g_scale0[k], g_shift0[k]));
        xs[k * STR + r] = v;
    }
    __syncthreads();

    int cg = t & 15, rg = t >> 4;                // 16 col-groups x 4 row-groups
    float acc[4][4] = {};
    const float4* w4 = reinterpret_cast<const float4*>(wT);
#pragma unroll 8
    for (int k = 0; k < K; k++) {
        float4 xv = *reinterpret_cast<const float4*>(&xs[k * STR + rg * 4]);
        float4 wv = __ldg(&w4[k * 16 + cg]);
        float xa[4] = {xv.x, xv.y, xv.z, xv.w};
        float wa[4] = {wv.x, wv.y, wv.z, wv.w};
#pragma unroll
        for (int r = 0; r < 4; r++)
#pragma unroll
            for (int c = 0; c < 4; c++)
                acc[r][c] = fmaf(xa[r], wa[c], acc[r][c]);
    }

    float* dst = (cg < 8) ? g_y1 : g_y2;
    int cb = (cg < 8) ? cg * 4 : (cg - 8) * 4;
#pragma unroll
    for (int r = 0; r < 4; r++) {
        int row = row0 + rg * 4 + r;
        float4 v = make_float4(acc[r][0], acc[r][1], acc[r][2], acc[r][3]);
        *reinterpret_cast<float4*>(&dst[row * 32 + cb]) = v;
    }
}

// ---------------- sparse graph conv: warp per (b,m), lane per channel ----------------
__global__ void k_conv(int layer)
{
    int warp = threadIdx.x >> 5, lane = threadIdx.x & 31;
    int pair = blockIdx.x * 8 + warp;            // pair = b*M + m
    int m    = pair & (MM - 1);
    const float* attn = layer ? g_attn1 : g_attn0;
    const float* bias = layer ? g_bias1 : g_bias0;
    float* out        = layer ? g_h1   : g_h0;
    int base = m * NNK;
    int boff = pair - m;                         // b*M
    float acc = bias[lane] + g_y2[pair * 32 + lane];
#pragma unroll
    for (int k = 0; k < NNK; k++) {
        float a  = __ldg(&attn[base + k]);
        int col  = __ldg(&g_cols[base + k]);
        acc = fmaf(a, g_y1[(boff + col) * 32 + lane], acc);
    }
    out[pair * 32 + lane] = acc;
}

// ---------------- BN stats (sum & sumsq per channel) ----------------
__global__ void k_stats(int layer)
{
    const float* h = layer ? g_h1 : g_h0;
    float* st = g_stats + layer * 64;
    int t = threadIdx.x;
    float s = 0.f, q = 0.f;
    for (int i = blockIdx.x * 256 + t; i < NEL; i += 65536) {
        float v = h[i];
        s += v; q = fmaf(v, v, q);
    }
    __shared__ float ss[256], sq[256];
    ss[t] = s; sq[t] = q;
    __syncthreads();
    if (t < 32) {
#pragma unroll
        for (int w = 1; w < 8; w++) { s += ss[t + 32*w]; q += sq[t + 32*w]; }
        atomicAdd(&st[t], s);
        atomicAdd(&st[32 + t], q);
    }
}

// ---------------- BN scale/shift from stats ----------------
__global__ void k_bnscale(int layer, const float* __restrict__ g, const float* __restrict__ b)
{
    int t = threadIdx.x;
    if (t >= 32) return;
    const float* st = g_stats + layer * 64;
    float inv_n = 1.f / (float)NROW;
    float mean = st[t] * inv_n;
    float var  = st[32 + t] * inv_n - mean * mean;
    float sc = g[t] * rsqrtf(var + 1e-5f);
    float sh = b[t] - mean * sc;
    if (layer) { g_scale1[t] = sc; g_shift1[t] = sh; }
    else       { g_scale0[t] = sc; g_shift0[t] = sh; }
}

// ---------------- FC1 split-K: grid (128 i-segments, 8 o-tiles of 32) ----------------
__global__ void __launch_bounds__(256) k_fc1(const float* __restrict__ w)
{
    __shared__ float fs[8 * 1024];
    int seg = blockIdx.x, ot = blockIdx.y, t = threadIdx.x;
    int ibase = seg * 1024;
    for (int idx = t; idx < 8192; idx += 256) {
        int b = idx >> 10, ii = idx & 1023;
        float v = g_h1[b * FCIN + ibase + ii];
        fs[idx] = fmaxf(0.f, fmaf(v, g_scale1[ii & 31], g_shift1[ii & 31]));
    }
    __syncthreads();

    int warp = t >> 5, lane = t & 31;
    int o0 = ot * 32 + warp * 4;
    float a[4][8] = {};
    for (int ii = lane; ii < 1024; ii += 32) {
        float f[8];
#pragma unroll
        for (int b = 0; b < 8; b++) f[b] = fs[b * 1024 + ii];
#pragma unroll
        for (int oo = 0; oo < 4; oo++) {
            float wv = __ldg(&w[(size_t)(o0 + oo) * FCIN + ibase + ii]);
#pragma unroll
            for (int b = 0; b < 8; b++) a[oo][b] = fmaf(wv, f[b], a[oo][b]);
        }
    }
#pragma unroll
    for (int oo = 0; oo < 4; oo++)
#pragma unroll
        for (int b = 0; b < 8; b++) {
            float v = a[oo][b];
#pragma unroll
            for (int off = 16; off; off >>= 1) v += __shfl_xor_sync(0xffffffffu, v, off);
            if (lane == 0) atomicAdd(&g_acc[b * HID + o0 + oo], v);
        }
}

// ---------------- FC2: out[b][j] = relu(acc+fc1b) . fc2w[j] + fc2b[j] ----------------
__global__ void k_fc2(const float* __restrict__ fc1b, const float* __restrict__ w2,
                      const float* __restrict__ b2, float* __restrict__ out)
{
    int j = blockIdx.x;                          // 0..52
    int b = threadIdx.x >> 5, lane = threadIdx.x & 31;
    float s = 0.f;
    for (int o = lane; o < HID; o += 32) {
        float a = fmaxf(0.f, g_acc[b * HID + o] + __ldg(&fc1b[o]));
        s = fmaf(a, __ldg(&w2[j * HID + o]), s);
    }
#pragma unroll
    for (int off = 16; off; off >>= 1) s += __shfl_xor_sync(0xffffffffu, s, off);
    if (lane == 0) out[b * NOUT + j] = s + b2[j];
}

// ---------------- launch ----------------
extern "C" void kernel_launch(void* const* d_in, const int* in_sizes, int n_in,
                              void* d_out, int out_size)
{
    const float* x      = (const float*)d_in[0];
    const float* pseudo = (const float*)d_in[1];
    const int*   L_idx  = (const int*)  d_in[2];
    const float* ew   = (const float*)d_in[3];
    const float* eb   = (const float*)d_in[4];
    const float* mu0  = (const float*)d_in[5];
    const float* sg0  = (const float*)d_in[6];
    const float* mu1  = (const float*)d_in[7];
    const float* sg1  = (const float*)d_in[8];
    const float* l1w0 = (const float*)d_in[9];
    const float* l1b0 = (const float*)d_in[10];
    const float* l2w0 = (const float*)d_in[11];
    const float* l2b0 = (const float*)d_in[12];
    const float* l1w1 = (const float*)d_in[13];
    const float* l1b1 = (const float*)d_in[14];
    const float* l2w1 = (const float*)d_in[15];
    const float* l2b1 = (const float*)d_in[16];
    const float* bng0 = (const float*)d_in[17];
    const float* bnb0 = (const float*)d_in[18];
    const float* bng1 = (const float*)d_in[19];
    const float* bnb1 = (const float*)d_in[20];
    const float* fc1w = (const float*)d_in[21];
    const float* fc1b = (const float*)d_in[22];
    const float* fc2w = (const float*)d_in[23];
    const float* fc2b = (const float*)d_in[24];
    float* out = (float*)d_out;

    k_zero<<<1, 256>>>();
    k_attn<<<NNE/256, 256>>>(pseudo, L_idx, ew, eb, mu0, sg0, mu1, sg1);
    k_prepw<<<1, 256>>>(l1w0, l1b0, l2w0, l2b0, l1w1, l1b1, l2w1, l2b1);

    // layer 0
    k_proj<128, false><<<NROW/16, 64>>>(x);
    k_conv<<<NROW/8, 256>>>(0);
    k_stats<<<256, 256>>>(0);
    k_bnscale<<<1, 32>>>(0, bng0, bnb0);

    // layer 1 (BN0+relu folded into proj staging)
    k_proj<32, true><<<NROW/16, 64>>>(x);
    k_conv<<<NROW/8, 256>>>(1);
    k_stats<<<256, 256>>>(1);
    k_bnscale<<<1, 32>>>(1, bng1, bnb1);

    // FC head (BN1+relu folded into fc1 staging)
    k_fc1<<<dim3(128, 8), 256>>>(fc1w);
    k_fc2<<<NOUT, 256>>>(fc1b, fc2w, fc2b, out);
}